// round 6
// baseline (speedup 1.0000x reference)
#include <cuda_runtime.h>
#include <cuda_bf16.h>

#define ROWS 4096
#define COLS 32000
#define NF4  (COLS / 4)                  // 8000 float4 per row
#define CAP  3072                        // compacted tail capacity (expected ~1200)
#define BD   256                         // block dim
#define VPT  2                           // float4 per thread per chunk
#define CHW  (BD * VPT)                  // float4 per chunk = 512
#define NCHUNK ((NF4 + CHW - 1) / CHW)   // 16 chunks (last partial)
#define NEG_INF (-3.402823466e38f)

// Monotone float<->uint mapping for atomicMax on floats (any sign).
__device__ __forceinline__ unsigned fenc(float f) {
    unsigned b = __float_as_uint(f);
    return b ^ ((unsigned)((int)b >> 31) | 0x80000000u);
}
__device__ __forceinline__ float fdec(unsigned u) {
    unsigned b = u ^ ((u & 0x80000000u) ? 0x80000000u : 0xFFFFFFFFu);
    return __uint_as_float(b);
}

// ---------------------------------------------------------------------------
// Fully fused, single-X-read kernel. One CTA (256 thr) per row.
//   Phase A: streaming read (2 float4/thread/chunk, double-buffered); per-chunk
//            running block max; filter chunk against (runmax*0.5 - 1) =>
//            superset of final support, compacted to smem. Warp-uniform
//            fast-path skips all compaction work when the warp's chunk max
//            cannot pass the filter. Over-kept elements contribute exactly 0
//            everywhere (xs <= max_s-1 < tau_m always).
//   Phase B: warp 0 bisects (50 iters) over compacted values while warps 1-7
//            zero-fill the output row (independent of tau).
//   Phase C: scatter the <=n nonzero probabilities (L2-hot lines).
// ---------------------------------------------------------------------------
__global__ __launch_bounds__(BD, 8) void entmax_onepass_kernel(const float* __restrict__ X,
                                                               float* __restrict__ out) {
    const int row = blockIdx.x;
    const float4* Xr = reinterpret_cast<const float4*>(X + (size_t)row * COLS);
    float4* Or = reinterpret_cast<float4*>(out + (size_t)row * COLS);

    __shared__ float    s_vals[CAP];
    __shared__ int      s_idx[CAP];
    __shared__ unsigned s_maxu;
    __shared__ int      s_count;
    __shared__ float    s_tau, s_invZ;

    const int tid  = threadIdx.x;
    const int lane = tid & 31;
    const int wrp  = tid >> 5;

    if (tid == 0) { s_maxu = fenc(NEG_INF); s_count = 0; }
    __syncthreads();

    const float4 neg4 = make_float4(NEG_INF, NEG_INF, NEG_INF, NEG_INF);

    // ---- Phase A: single pass — running max + superset compaction
    float4 v0 = Xr[tid];                  // chunk 0 fully in-bounds (CHW=512 <= NF4)
    float4 v1 = Xr[tid + BD];
    #pragma unroll 1
    for (int c = 0; c < NCHUNK; c++) {
        const int base0 = c * CHW + tid;        // first float4 index
        const int base1 = base0 + BD;           // second float4 index
        // double-buffer: issue next chunk's loads before the barrier
        float4 n0 = neg4, n1 = neg4;
        if (c + 1 < NCHUNK) {
            const int b0 = base0 + CHW, b1 = base1 + CHW;
            if (b0 < NF4) n0 = Xr[b0];
            if (b1 < NF4) n1 = Xr[b1];
        }

        const bool val0 = (base0 < NF4);
        const bool val1 = (base1 < NF4);
        float tm = NEG_INF;
        if (val0) tm = fmaxf(tm, fmaxf(fmaxf(v0.x, v0.y), fmaxf(v0.z, v0.w)));
        if (val1) tm = fmaxf(tm, fmaxf(fmaxf(v1.x, v1.y), fmaxf(v1.z, v1.w)));
        #pragma unroll
        for (int o = 16; o > 0; o >>= 1)
            tm = fmaxf(tm, __shfl_xor_sync(0xFFFFFFFFu, tm, o));
        if (lane == 0) atomicMax(&s_maxu, fenc(tm));
        __syncthreads();   // running max now includes all chunks <= c

        const float thresh = fdec(s_maxu) * 0.5f - 1.0f;  // <= final thresh => superset

        // warp-uniform fast path: warp's chunk max can't pass => skip compaction
        if (tm * 0.5f > thresh) {
            const float xs[8] = {v0.x * 0.5f, v0.y * 0.5f, v0.z * 0.5f, v0.w * 0.5f,
                                 v1.x * 0.5f, v1.y * 0.5f, v1.z * 0.5f, v1.w * 0.5f};
            #pragma unroll
            for (int k = 0; k < 8; k++) {
                const bool vk = (k < 4) ? val0 : val1;
                const int  gi = ((k < 4) ? base0 : base1) * 4 + (k & 3);
                const bool p  = vk && (xs[k] > thresh);
                const unsigned mask = __ballot_sync(0xFFFFFFFFu, p);
                if (mask == 0u) continue;
                if (p) {
                    const int rank   = __popc(mask & ((1u << lane) - 1u));
                    const int leader = __ffs(mask) - 1;
                    int base = 0;
                    if (lane == leader) base = atomicAdd(&s_count, __popc(mask));
                    base = __shfl_sync(mask, base, leader);
                    const int idx = base + rank;
                    if (idx < CAP) {
                        s_vals[idx] = xs[k];
                        s_idx[idx]  = gi;
                    }
                }
            }
        }
        v0 = n0; v1 = n1;
    }
    __syncthreads();

    const float max_s = fdec(s_maxu) * 0.5f;   // max_val * (alpha-1), exact: *0.5
    const int   cnt   = s_count;
    const int   n     = (cnt < CAP) ? cnt : CAP;
    const bool  ovf   = (cnt > CAP);           // practically impossible; exact fallback

    // ---- Phase B: warp 0 bisects; warps 1..7 zero-fill output concurrently
    if (wrp == 0) {
        float tau_lo = max_s - 1.0f;
        const float tau_hi = max_s - 0.005590169943749474f;  // max_s - (1/d)^(alpha-1)
        float dm = tau_hi - tau_lo;
        float tau_m = tau_lo;
        float Z = 1.0f;
        const float* Xrow = X + (size_t)row * COLS;

        #pragma unroll 1
        for (int it = 0; it < 50; it++) {
            dm *= 0.5f;
            tau_m = tau_lo + dm;
            float acc = 0.0f;
            if (!ovf) {
                #pragma unroll 8
                for (int j = lane; j < n; j += 32) {
                    float t = fmaxf(s_vals[j] - tau_m, 0.0f);
                    acc = fmaf(t, t, acc);
                }
            } else {
                for (int j = lane; j < COLS; j += 32) {
                    float t = fmaxf(fmaf(Xrow[j], 0.5f, -tau_m), 0.0f);
                    acc = fmaf(t, t, acc);
                }
            }
            #pragma unroll
            for (int o = 16; o > 0; o >>= 1)
                acc += __shfl_xor_sync(0xFFFFFFFFu, acc, o);
            if (acc - 1.0f >= 0.0f) tau_lo = tau_m;
            Z = acc;   // sum at this iteration's tau_m (matches reference's final p_m)
        }
        if (lane == 0) { s_tau = tau_m; s_invZ = 1.0f / Z; }
    } else if (!ovf) {
        const float4 z4 = make_float4(0.0f, 0.0f, 0.0f, 0.0f);
        for (int i = tid - 32; i < NF4; i += BD - 32)
            Or[i] = z4;
    }
    __syncthreads();

    const float tau  = s_tau;
    const float invZ = s_invZ;

    // ---- Phase C: output
    if (!ovf) {
        float* Orow = out + (size_t)row * COLS;
        for (int j = tid; j < n; j += BD) {
            const float t = fmaxf(s_vals[j] - tau, 0.0f);
            Orow[s_idx[j]] = t * t * invZ;
        }
    } else {
        for (int i = tid; i < NF4; i += BD) {
            float4 xv = Xr[i];
            float4 o; float t;
            t = fmaxf(xv.x * 0.5f - tau, 0.0f); o.x = t * t * invZ;
            t = fmaxf(xv.y * 0.5f - tau, 0.0f); o.y = t * t * invZ;
            t = fmaxf(xv.z * 0.5f - tau, 0.0f); o.z = t * t * invZ;
            t = fmaxf(xv.w * 0.5f - tau, 0.0f); o.w = t * t * invZ;
            Or[i] = o;
        }
    }
}

// ---------------------------------------------------------------------------
extern "C" void kernel_launch(void* const* d_in, const int* in_sizes, int n_in,
                              void* d_out, int out_size) {
    const float* X = (const float*)d_in[0];
    float* out = (float*)d_out;
    entmax_onepass_kernel<<<ROWS, BD>>>(X, out);
}

// round 9
// speedup vs baseline: 1.0764x; 1.0764x over previous
#include <cuda_runtime.h>
#include <cuda_bf16.h>

#define ROWS 4096
#define COLS 32000
#define NF4  (COLS / 4)                  // 8000 float4 per row
#define CAP  3072                        // compacted tail capacity (expected ~2000)
#define BD   256                         // block dim
#define VPT  2                           // float4 per thread per chunk
#define CHW  (BD * VPT)                  // float4 per chunk = 512
#define NCHUNK ((NF4 + CHW - 1) / CHW)   // 16 chunks (last partial)
#define NEG_INF (-3.402823466e38f)

// Monotone float<->uint mapping for atomicMax on floats (any sign).
__device__ __forceinline__ unsigned fenc(float f) {
    unsigned b = __float_as_uint(f);
    return b ^ ((unsigned)((int)b >> 31) | 0x80000000u);
}
__device__ __forceinline__ float fdec(unsigned u) {
    unsigned b = u ^ ((u & 0x80000000u) ? 0x80000000u : 0xFFFFFFFFu);
    return __uint_as_float(b);
}

// ---------------------------------------------------------------------------
// Single-X-read kernel, BARRIER-FREE streaming with register prefetch.
// One CTA (256 thr) per row.
//   Phase A: warps free-run over the row (no BAR.SYNC in the loop). Shared
//            running max via atomicMax; its return value gives each warp the
//            current block max without a barrier. Filter each chunk against
//            (runmax*0.5 - 1): monotone lower bound of the final threshold
//            => superset of the true support (over-kept elements are exactly
//            0 in every sum and in the output). Next chunk is prefetched into
//            registers before the compaction work of the current chunk.
//   Phase B: warp 0 bisects (50 iters) over compacted values while warps 1-7
//            zero-fill the output row (independent of tau).
//   Phase C: scatter <=n nonzero probabilities (lines still L2-resident).
// ---------------------------------------------------------------------------
__global__ __launch_bounds__(BD, 8) void entmax_onepass_kernel(const float* __restrict__ X,
                                                               float* __restrict__ out) {
    const int row = blockIdx.x;
    const float4* Xr = reinterpret_cast<const float4*>(X + (size_t)row * COLS);
    float4* Or = reinterpret_cast<float4*>(out + (size_t)row * COLS);

    __shared__ float    s_vals[CAP];
    __shared__ int      s_idx[CAP];
    __shared__ unsigned s_maxu;
    __shared__ int      s_count;
    __shared__ float    s_tau, s_invZ;

    const int tid  = threadIdx.x;
    const int lane = tid & 31;
    const int wrp  = tid >> 5;

    if (tid == 0) { s_maxu = fenc(NEG_INF); s_count = 0; }
    __syncthreads();

    const float4 neg4 = make_float4(NEG_INF, NEG_INF, NEG_INF, NEG_INF);

    // ---- Phase A, chunk 0 (fully in-bounds): seed block max, one barrier
    float4 v0 = Xr[tid];
    float4 v1 = Xr[tid + BD];
    // prefetch chunk 1 before chunk-0 processing
    float4 p0 = Xr[tid + CHW];
    float4 p1 = Xr[tid + CHW + BD];
    {
        float tm = fmaxf(fmaxf(fmaxf(v0.x, v0.y), fmaxf(v0.z, v0.w)),
                         fmaxf(fmaxf(v1.x, v1.y), fmaxf(v1.z, v1.w)));
        #pragma unroll
        for (int o = 16; o > 0; o >>= 1)
            tm = fmaxf(tm, __shfl_xor_sync(0xFFFFFFFFu, tm, o));
        if (lane == 0) atomicMax(&s_maxu, fenc(tm));
        __syncthreads();                       // block max over first 2048 elems
        const float thresh = fdec(s_maxu) * 0.5f - 1.0f;
        if (tm * 0.5f > thresh) {
            const float xs[8] = {v0.x * 0.5f, v0.y * 0.5f, v0.z * 0.5f, v0.w * 0.5f,
                                 v1.x * 0.5f, v1.y * 0.5f, v1.z * 0.5f, v1.w * 0.5f};
            #pragma unroll
            for (int k = 0; k < 8; k++) {
                const int gi = (((k < 4) ? tid : tid + BD)) * 4 + (k & 3);
                const bool p = (xs[k] > thresh);
                const unsigned mask = __ballot_sync(0xFFFFFFFFu, p);
                if (mask == 0u) continue;
                if (p) {
                    const int rank   = __popc(mask & ((1u << lane) - 1u));
                    const int leader = __ffs(mask) - 1;
                    int base = 0;
                    if (lane == leader) base = atomicAdd(&s_count, __popc(mask));
                    base = __shfl_sync(mask, base, leader);
                    const int idx = base + rank;
                    if (idx < CAP) { s_vals[idx] = xs[k]; s_idx[idx] = gi; }
                }
            }
        }
    }

    // ---- Phase A, chunks 1..15: barrier-free, prefetched stream
    #pragma unroll 1
    for (int c = 1; c < NCHUNK; c++) {
        const int base0 = c * CHW + tid;
        const int base1 = base0 + BD;
        const bool val0 = (base0 < NF4);
        const bool val1 = (base1 < NF4);
        float4 w0 = p0, w1 = p1;

        // prefetch chunk c+1 before any dependent work on chunk c
        p0 = neg4; p1 = neg4;
        if (c + 1 < NCHUNK) {
            const int b0 = base0 + CHW, b1 = base1 + CHW;
            if (b0 < NF4) p0 = Xr[b0];
            if (b1 < NF4) p1 = Xr[b1];
        }
        if (!val0) w0 = neg4;
        if (!val1) w1 = neg4;

        float tm = fmaxf(fmaxf(fmaxf(w0.x, w0.y), fmaxf(w0.z, w0.w)),
                         fmaxf(fmaxf(w1.x, w1.y), fmaxf(w1.z, w1.w)));
        #pragma unroll
        for (int o = 16; o > 0; o >>= 1)
            tm = fmaxf(tm, __shfl_xor_sync(0xFFFFFFFFu, tm, o));
        unsigned old = 0;
        if (lane == 0) old = atomicMax(&s_maxu, fenc(tm));
        old = __shfl_sync(0xFFFFFFFFu, old, 0);
        const float m = fmaxf(fdec(old), tm);          // current block running max
        const float thresh = m * 0.5f - 1.0f;          // <= final thresh => superset

        if (tm * 0.5f > thresh) {                      // warp-uniform skip
            const float xs[8] = {w0.x * 0.5f, w0.y * 0.5f, w0.z * 0.5f, w0.w * 0.5f,
                                 w1.x * 0.5f, w1.y * 0.5f, w1.z * 0.5f, w1.w * 0.5f};
            #pragma unroll
            for (int k = 0; k < 8; k++) {
                const bool vk = (k < 4) ? val0 : val1;
                const int  gi = ((k < 4) ? base0 : base1) * 4 + (k & 3);
                const bool p  = vk && (xs[k] > thresh);
                const unsigned mask = __ballot_sync(0xFFFFFFFFu, p);
                if (mask == 0u) continue;
                if (p) {
                    const int rank   = __popc(mask & ((1u << lane) - 1u));
                    const int leader = __ffs(mask) - 1;
                    int base = 0;
                    if (lane == leader) base = atomicAdd(&s_count, __popc(mask));
                    base = __shfl_sync(mask, base, leader);
                    const int idx = base + rank;
                    if (idx < CAP) { s_vals[idx] = xs[k]; s_idx[idx] = gi; }
                }
            }
        }
    }
    __syncthreads();

    const float max_s = fdec(s_maxu) * 0.5f;   // max_val * (alpha-1), exact: *0.5
    const int   cnt   = s_count;
    const int   n     = (cnt < CAP) ? cnt : CAP;
    const bool  ovf   = (cnt > CAP);           // rare; exact full-row fallback

    // ---- Phase B: warp 0 bisects; warps 1..7 zero-fill output concurrently
    if (wrp == 0) {
        float tau_lo = max_s - 1.0f;
        const float tau_hi = max_s - 0.005590169943749474f;  // max_s - (1/d)^(alpha-1)
        float dm = tau_hi - tau_lo;
        float tau_m = tau_lo;
        float Z = 1.0f;
        const float* Xrow = X + (size_t)row * COLS;

        #pragma unroll 1
        for (int it = 0; it < 50; it++) {
            dm *= 0.5f;
            tau_m = tau_lo + dm;
            float acc = 0.0f;
            if (!ovf) {
                #pragma unroll 8
                for (int j = lane; j < n; j += 32) {
                    float t = fmaxf(s_vals[j] - tau_m, 0.0f);
                    acc = fmaf(t, t, acc);
                }
            } else {
                for (int j = lane; j < COLS; j += 32) {
                    float t = fmaxf(fmaf(Xrow[j], 0.5f, -tau_m), 0.0f);
                    acc = fmaf(t, t, acc);
                }
            }
            #pragma unroll
            for (int o = 16; o > 0; o >>= 1)
                acc += __shfl_xor_sync(0xFFFFFFFFu, acc, o);
            if (acc - 1.0f >= 0.0f) tau_lo = tau_m;
            Z = acc;   // sum at this iteration's tau_m (matches reference's final p_m)
        }
        if (lane == 0) { s_tau = tau_m; s_invZ = 1.0f / Z; }
    } else if (!ovf) {
        const float4 z4 = make_float4(0.0f, 0.0f, 0.0f, 0.0f);
        for (int i = tid - 32; i < NF4; i += BD - 32)
            Or[i] = z4;
    }
    __syncthreads();

    const float tau  = s_tau;
    const float invZ = s_invZ;

    // ---- Phase C: output
    if (!ovf) {
        float* Orow = out + (size_t)row * COLS;
        for (int j = tid; j < n; j += BD) {
            const float t = fmaxf(s_vals[j] - tau, 0.0f);
            Orow[s_idx[j]] = t * t * invZ;
        }
    } else {
        for (int i = tid; i < NF4; i += BD) {
            float4 xv = Xr[i];
            float4 o; float t;
            t = fmaxf(xv.x * 0.5f - tau, 0.0f); o.x = t * t * invZ;
            t = fmaxf(xv.y * 0.5f - tau, 0.0f); o.y = t * t * invZ;
            t = fmaxf(xv.z * 0.5f - tau, 0.0f); o.z = t * t * invZ;
            t = fmaxf(xv.w * 0.5f - tau, 0.0f); o.w = t * t * invZ;
            Or[i] = o;
        }
    }
}

// ---------------------------------------------------------------------------
extern "C" void kernel_launch(void* const* d_in, const int* in_sizes, int n_in,
                              void* d_out, int out_size) {
    const float* X = (const float*)d_in[0];
    float* out = (float*)d_out;
    entmax_onepass_kernel<<<ROWS, BD>>>(X, out);
}